// round 8
// baseline (speedup 1.0000x reference)
#include <cuda_runtime.h>
#include <cuda_bf16.h>
#include <cstdint>
#include <math.h>

// Problem constants
#define BB 64
#define SS 512
#define II 512
#define HH 512
#define LL 2
#define MROWS (BB * LL)          // 128 recurrence rows
#define MX (BB * SS)             // 32768 rows of xa GEMM

// ---------------- scratch (static device memory; no allocs allowed) ----------
__device__ float g_xa[(size_t)MX * HH];       // 64 MB: xa = x @ W_ih^T + b_ih

// =============================================================================
// Kernel A: xa[m][n] = sum_k x[m][k] * W_ih[n][k] + b_ih[n]
// 128x128 tile, BK=8, double buffered, 8x8 per thread, 256 threads.
// =============================================================================
__global__ void __launch_bounds__(256) gemm_xa_kernel(
    const float* __restrict__ A,      // [MX][II]
    const float* __restrict__ Bw,     // [HH][II]
    const float* __restrict__ bias)   // [HH]
{
    __shared__ float As[2][8][128];
    __shared__ float Bs[2][8][128];

    const int K = II;
    const int N = HH;
    const int m0 = blockIdx.y * 128;
    const int n0 = blockIdx.x * 128;
    const int tid = threadIdx.x;
    const int tx = tid & 15;
    const int ty = tid >> 4;
    const int lrow = tid >> 1;
    const int lkq  = (tid & 1) * 4;

    const float* Aptr = A + (size_t)(m0 + lrow) * K + lkq;
    const float* Bptr = Bw + (size_t)(n0 + lrow) * K + lkq;

    float acc[8][8];
#pragma unroll
    for (int i = 0; i < 8; i++)
#pragma unroll
        for (int j = 0; j < 8; j++) acc[i][j] = 0.f;

    {
        float4 av = *(const float4*)Aptr;
        float4 bv = *(const float4*)Bptr;
        As[0][lkq + 0][lrow] = av.x; As[0][lkq + 1][lrow] = av.y;
        As[0][lkq + 2][lrow] = av.z; As[0][lkq + 3][lrow] = av.w;
        Bs[0][lkq + 0][lrow] = bv.x; Bs[0][lkq + 1][lrow] = bv.y;
        Bs[0][lkq + 2][lrow] = bv.z; Bs[0][lkq + 3][lrow] = bv.w;
    }
    __syncthreads();

    for (int kb = 8; kb <= K; kb += 8) {
        const int buf = ((kb >> 3) & 1) ^ 1;
        float4 av2, bv2;
        const bool more = (kb < K);
        if (more) {
            av2 = *(const float4*)(Aptr + kb);
            bv2 = *(const float4*)(Bptr + kb);
        }
#pragma unroll
        for (int kk = 0; kk < 8; kk++) {
            float a[8], b[8];
            *(float4*)(a + 0) = *(const float4*)&As[buf][kk][ty * 8 + 0];
            *(float4*)(a + 4) = *(const float4*)&As[buf][kk][ty * 8 + 4];
            *(float4*)(b + 0) = *(const float4*)&Bs[buf][kk][tx * 8 + 0];
            *(float4*)(b + 4) = *(const float4*)&Bs[buf][kk][tx * 8 + 4];
#pragma unroll
            for (int i = 0; i < 8; i++)
#pragma unroll
                for (int j = 0; j < 8; j++)
                    acc[i][j] += a[i] * b[j];
        }
        if (more) {
            const int nb = buf ^ 1;
            As[nb][lkq + 0][lrow] = av2.x; As[nb][lkq + 1][lrow] = av2.y;
            As[nb][lkq + 2][lrow] = av2.z; As[nb][lkq + 3][lrow] = av2.w;
            Bs[nb][lkq + 0][lrow] = bv2.x; Bs[nb][lkq + 1][lrow] = bv2.y;
            Bs[nb][lkq + 2][lrow] = bv2.z; Bs[nb][lkq + 3][lrow] = bv2.w;
            __syncthreads();
        }
    }

    float4 bv0 = *(const float4*)&bias[n0 + tx * 8 + 0];
    float4 bv1 = *(const float4*)&bias[n0 + tx * 8 + 4];
#pragma unroll
    for (int i = 0; i < 8; i++) {
        float* Crow = g_xa + (size_t)(m0 + ty * 8 + i) * N + n0 + tx * 8;
        float4 c0, c1;
        c0.x = acc[i][0] + bv0.x; c0.y = acc[i][1] + bv0.y;
        c0.z = acc[i][2] + bv0.z; c0.w = acc[i][3] + bv0.w;
        c1.x = acc[i][4] + bv1.x; c1.y = acc[i][5] + bv1.y;
        c1.z = acc[i][6] + bv1.z; c1.w = acc[i][7] + bv1.w;
        *(float4*)(Crow + 0) = c0;
        *(float4*)(Crow + 4) = c1;
    }
}

// =============================================================================
// Kernel B: persistent recurrence, v5 (DSMEM cluster push).
// grid 128 = 16 clusters of 8 CTAs. Cluster = one row-group (rb = bid>>3);
// CTA rank = gb = bid&7 owns cols gb*64..+63, rows rb*8..+7, K=512.
// Each CTA pushes its computed 8x64 h-slice into ALL 8 cluster CTAs' smem
// (st.shared::cluster), double-buffered, signaled via cluster mbarriers.
// No global h, no L2 barrier, no re-stage.
// SMEM: Wt[512][64] (128 KB), hs[2][8][516], red[8][512], 2 mbarriers.
// Compute mapping identical to round-3 (4x4 tile per thread, 8-way K split).
// =============================================================================
#define GB_CTAS 128
#define CLU 8

#define HS_STRIDE 516
#define HS_BUF_FLOATS (8 * HS_STRIDE)               // 4128
#define OFF_HS   (512 * 64)                          // floats
#define OFF_RED  (OFF_HS + 2 * HS_BUF_FLOATS)
#define OFF_MBAR (OFF_RED + 8 * 512)                 // 16B-aligned (float idx mult of 4)
#define SMEMB_FLOATS (OFF_MBAR + 4)

__device__ __forceinline__ unsigned smem_u32(const void* p) {
    unsigned a;
    asm("{ .reg .u64 t; cvta.to.shared.u64 t, %1; cvt.u32.u64 %0, t; }"
        : "=r"(a) : "l"(p));
    return a;
}

// cluster-scope parity wait (acquire.cluster: makes peers' DSMEM stores visible)
#define WAITC(mb, par) do {                                                     \
    unsigned _d;                                                                \
    asm volatile("{\n\t.reg .pred p;\n\t"                                       \
        "mbarrier.try_wait.parity.acquire.cluster.shared::cta.b64 p, [%1], %2;\n\t" \
        "selp.b32 %0, 1, 0, p;\n\t}"                                            \
        : "=r"(_d) : "r"(mb), "r"(par) : "memory");                             \
    if (!_d) {                                                                  \
        asm volatile("{\n\t.reg .pred P1;\n\t"                                  \
            "W_%=:\n\t"                                                         \
            "mbarrier.try_wait.parity.acquire.cluster.shared::cta.b64 P1, [%0], %1, 0x989680;\n\t" \
            "@P1 bra.uni D_%=;\n\t"                                             \
            "bra.uni W_%=;\n\t"                                                 \
            "D_%=:\n\t}"                                                        \
            :: "r"(mb), "r"(par) : "memory");                                   \
    }                                                                           \
} while (0)

__global__ void __launch_bounds__(256, 1) __cluster_dims__(CLU, 1, 1)
rnn_persistent_kernel(
    const float* __restrict__ W_hh,   // [HH][HH]
    const float* __restrict__ b_hh,   // [HH]
    float* __restrict__ out)          // y then h_last
{
    extern __shared__ float sm[];
    float* Wt  = sm;                    // [512][64]  Wt[k][c] = W_hh[g0+c][k]
    float* hs  = sm + OFF_HS;           // [2][8][516]
    float* red = sm + OFF_RED;          // [8 kq][512 outputs]
    const unsigned mbar_u32 = smem_u32(sm + OFF_MBAR);  // two u64 mbarriers

    const int tid = threadIdx.x;
    const int gb  = blockIdx.x & 7;    // cluster rank = col-block
    const int rb  = blockIdx.x >> 3;   // cluster id  = row-group
    const int g0  = gb * 64;
    const int row_base = rb * 8;

    // ---- mbarrier init (arrive count = 8 producers per phase) ----
    if (tid == 0) {
        asm volatile("mbarrier.init.shared.b64 [%0], %1;" :: "r"(mbar_u32), "r"(8u) : "memory");
        asm volatile("mbarrier.init.shared.b64 [%0], %1;" :: "r"(mbar_u32 + 8), "r"(8u) : "memory");
    }

    // ---- one-time: load W slice transposed into smem (col-fast) ----
    {
        const int c  = tid & 63;
        const int k0 = tid >> 6;       // 0..3
        const float* wsrc = W_hh + (size_t)(g0 + c) * HH;
#pragma unroll 8
        for (int k = k0; k < 512; k += 4)
            Wt[k * 64 + c] = __ldg(wsrc + k);
    }
    __syncthreads();
    // all mbarriers in the cluster initialized before any remote arrive
    asm volatile("barrier.cluster.arrive.aligned;" ::: "memory");
    asm volatile("barrier.cluster.wait.aligned;" ::: "memory");

    // ---- compute-role indices (round-3 mapping) ----
    const int kq    = tid >> 5;        // warp id = K-slice of 64
    const int rowg  = (tid >> 4) & 1;
    const int colg  = tid & 15;
    const int kbase = kq * 64;
    const int r0    = rowg * 4;
    const int c0    = colg * 4;

    // ---- epilogue-role indices: outputs o = 2*tid, 2*tid+1 ----
    const int orow  = tid >> 5;        // local row 0..7 (one per warp)
    const int oc    = 2 * (tid & 31);  // local col pair
    const int grow  = row_base + orow; // global recurrence row
    const int b_idx = grow >> 1;       // batch
    const int l_idx = grow & 1;        // layer
    const int gcol  = g0 + oc;         // global column pair base

    const float2 bg  = *(const float2*)&b_hh[gcol];
    float2 xav = *(const float2*)&g_xa[((size_t)b_idx * SS + 0) * HH + gcol];

    // ---- precompute remote DSMEM addresses of my h slot in each rank ----
    // my slot inside hs[0]: row orow, columns gcol (= g0 + oc) of the 512-wide row
    unsigned slot_local = smem_u32(hs) + (unsigned)(orow * HS_STRIDE + gcol) * 4u;
    unsigned rem[CLU];
#pragma unroll
    for (int r = 0; r < CLU; r++)
        asm("mapa.shared::cluster.u32 %0, %1, %2;"
            : "=r"(rem[r]) : "r"(slot_local), "r"(r));

    const size_t Y_ELEMS = (size_t)BB * SS * LL * HH;
    int p0 = 0, p1 = 0;                // parity trackers for mbar[0], mbar[1]

    for (int s = 0; s < SS; s++) {
        float v0, v1;
        if (s == 0) {
            v0 = tanhf(xav.x + bg.x);
            v1 = tanhf(xav.y + bg.y);
        } else {
            // wait for all 8 producers' slices for this step (buf s&1)
            if (s & 1) { WAITC(mbar_u32 + 8, p1); p1 ^= 1; }
            else       { WAITC(mbar_u32 + 0, p0); p0 ^= 1; }

            // compute 4x4 tile over K-slice [kbase, kbase+64)
            float acc[4][4];
#pragma unroll
            for (int i = 0; i < 4; i++)
#pragma unroll
                for (int j = 0; j < 4; j++) acc[i][j] = 0.f;

            const float* hp = hs + (s & 1) * HS_BUF_FLOATS + r0 * HS_STRIDE + kbase;
            const float* wp = Wt + kbase * 64 + c0;
#pragma unroll 2
            for (int k = 0; k < 64; k += 4) {
                const float4 w0 = *(const float4*)(wp + (k + 0) * 64);
                const float4 w1 = *(const float4*)(wp + (k + 1) * 64);
                const float4 w2 = *(const float4*)(wp + (k + 2) * 64);
                const float4 w3 = *(const float4*)(wp + (k + 3) * 64);
                const float4 h0 = *(const float4*)(hp + 0 * HS_STRIDE + k);
                const float4 h1 = *(const float4*)(hp + 1 * HS_STRIDE + k);
                const float4 h2 = *(const float4*)(hp + 2 * HS_STRIDE + k);
                const float4 h3 = *(const float4*)(hp + 3 * HS_STRIDE + k);
#pragma unroll
                for (int j = 0; j < 4; j++) {
                    const float w0j = (&w0.x)[j], w1j = (&w1.x)[j];
                    const float w2j = (&w2.x)[j], w3j = (&w3.x)[j];
                    acc[0][j] += h0.x * w0j + h0.y * w1j + h0.z * w2j + h0.w * w3j;
                    acc[1][j] += h1.x * w0j + h1.y * w1j + h1.z * w2j + h1.w * w3j;
                    acc[2][j] += h2.x * w0j + h2.y * w1j + h2.z * w2j + h2.w * w3j;
                    acc[3][j] += h3.x * w0j + h3.y * w1j + h3.z * w2j + h3.w * w3j;
                }
            }

            // scatter partials: red[kq][(r0+i)*64 + c0..+3]  (STS.128)
            float* rp = red + kq * 512 + r0 * 64 + c0;
#pragma unroll
            for (int i = 0; i < 4; i++)
                *(float4*)(rp + i * 64) = *(float4*)acc[i];
            __syncthreads();

            // reduce over 8 kq slices for outputs (orow, oc/oc+1)
            const float* q = red + orow * 64 + oc;
            float a0 = 0.f, a1 = 0.f;
#pragma unroll
            for (int z = 0; z < 8; z++) {
                const float2 p = *(const float2*)(q + z * 512);
                a0 += p.x; a1 += p.y;
            }
            v0 = tanhf(a0 + xav.x + bg.x);
            v1 = tanhf(a1 + xav.y + bg.y);
        }

        if (s < SS - 1) {
            // push (v0,v1) into buf (s+1)&1 of ALL cluster CTAs (incl. self)
            const unsigned boff = (unsigned)(((s + 1) & 1) * HS_BUF_FLOATS * 4);
#pragma unroll
            for (int r = 0; r < CLU; r++)
                asm volatile("st.shared::cluster.v2.f32 [%0], {%1, %2};"
                             :: "r"(rem[r] + boff), "f"(v0), "f"(v1) : "memory");
            __syncthreads();   // all threads' remote stores issued

            // one arrive per target rank (release orders the CTA's stores)
            if (tid < CLU) {
                const unsigned mb = mbar_u32 + (((s + 1) & 1) ? 8u : 0u);
                asm volatile("{\n\t.reg .b32 r;\n\t"
                    "mapa.shared::cluster.u32 r, %0, %1;\n\t"
                    "mbarrier.arrive.release.cluster.shared::cluster.b64 _, [r];\n\t}"
                    :: "r"(mb), "r"(tid) : "memory");
            }
        }

        // epilogue (overlaps peers' waits): y writes + next xa prefetch
        {
            float2 yv; yv.x = v0; yv.y = v1;
            *(float2*)&out[(((size_t)b_idx * SS + s) * LL + l_idx) * HH + gcol] = yv;
            if (s == SS - 1) {
                *(float2*)&out[Y_ELEMS + (size_t)grow * HH + gcol] = yv;
            } else {
                xav = *(const float2*)&g_xa[((size_t)b_idx * SS + (s + 1)) * HH + gcol];
            }
        }
    }
}

// =============================================================================
// launch
// =============================================================================
extern "C" void kernel_launch(void* const* d_in, const int* in_sizes, int n_in,
                              void* d_out, int out_size)
{
    const float* x    = (const float*)d_in[0];
    const float* W_ih = (const float*)d_in[1];
    const float* b_ih = (const float*)d_in[2];
    const float* W_hh = (const float*)d_in[3];
    const float* b_hh = (const float*)d_in[4];
    float* out = (float*)d_out;

    // Kernel A: xa = x @ W_ih^T + b_ih
    dim3 gridA(HH / 128, MX / 128);
    gemm_xa_kernel<<<gridA, 256>>>(x, W_ih, b_ih);

    // Kernel B: persistent recurrence (16 independent clusters of 8)
    const int smemB = SMEMB_FLOATS * (int)sizeof(float);
    cudaFuncSetAttribute(rnn_persistent_kernel,
                         cudaFuncAttributeMaxDynamicSharedMemorySize, smemB);
    rnn_persistent_kernel<<<GB_CTAS, 256, smemB>>>(W_hh, b_hh, out);
}